// round 2
// baseline (speedup 1.0000x reference)
#include <cuda_runtime.h>

// Problem shape (fixed by reference): B=64, M=64, P=128, V=32.
// Output = 0.5 * min over (m,p) of point-polygon distance, BATCH 63 ONLY.
#define BN 64
#define MN 64
#define PN 128
#define VN 32
#define EPSF 1e-12f

__global__ void pl_init_kernel(unsigned int* __restrict__ out) {
    out[0] = 0x7F800000u;  // +inf bit pattern
}

__global__ void pl_main_kernel(const float* __restrict__ last_point,
                               const float* __restrict__ polygon_coords,
                               unsigned int* __restrict__ out) {
    // One block per polygon p, one thread per point m.
    __shared__ float2 s_a[VN];
    __shared__ float2 s_b[VN];
    __shared__ float  s_inv2[VN];    // 1 / (|ab|^2 + eps)
    __shared__ float  s_invdy[VN];   // 1 / (by - ay + eps)
    __shared__ float  s_warpmin[MN / 32];

    const int p = blockIdx.x;
    const int t = threadIdx.x;

    // Polygon p of batch 63: vertices are contiguous float2.
    const float2* pc = reinterpret_cast<const float2*>(polygon_coords)
                       + ( ( (BN - 1) * PN + p ) * VN );

    if (t < VN) {
        float2 a = pc[t];
        float2 b = pc[(t + 1) & (VN - 1)];   // roll(-1) over vertex axis
        s_a[t] = a;
        s_b[t] = b;
        float abx = b.x - a.x;
        float aby = b.y - a.y;
        s_inv2[t]  = 1.0f / (abx * abx + aby * aby + EPSF);
        s_invdy[t] = 1.0f / (aby + EPSF);
    }
    __syncthreads();

    // This thread's query point: last_point[63, t, :]
    const float2 pt = reinterpret_cast<const float2*>(last_point)[(BN - 1) * MN + t];
    const float px = pt.x;
    const float py = pt.y;

    float mindd = 3.402823466e+38f;
    int crossings = 0;

#pragma unroll
    for (int v = 0; v < VN; ++v) {
        const float2 a = s_a[v];
        const float2 b = s_b[v];
        const float abx = b.x - a.x;
        const float aby = b.y - a.y;
        const float apx = px - a.x;
        const float apy = py - a.y;

        // Segment distance (squared; sqrt deferred — monotone)
        float tt = (apx * abx + apy * aby) * s_inv2[v];
        tt = fminf(fmaxf(tt, 0.0f), 1.0f);
        const float dx = apx - tt * abx;
        const float dy = apy - tt * aby;
        const float dd = dx * dx + dy * dy;
        mindd = fminf(mindd, dd);

        // Ray-crossing (even-odd) test
        const bool straddles = (a.y > py) != (b.y > py);
        const float x_int = a.x + abx * (py - a.y) * s_invdy[v];
        if (straddles && (px < x_int)) ++crossings;
    }

    const bool inside = (crossings & 1) != 0;
    float val = inside ? 0.0f : sqrtf(fmaxf(mindd, EPSF));

    // Block min-reduction: warp shuffles, then across the 2 warps.
#pragma unroll
    for (int off = 16; off > 0; off >>= 1)
        val = fminf(val, __shfl_xor_sync(0xFFFFFFFFu, val, off));
    if ((t & 31) == 0) s_warpmin[t >> 5] = val;
    __syncthreads();

    if (t == 0) {
        float m = s_warpmin[0];
#pragma unroll
        for (int w = 1; w < MN / 32; ++w) m = fminf(m, s_warpmin[w]);
        // All candidates >= 0 -> IEEE bit order == numeric order.
        // Scale by loss weight BEFORE the min (monotone), avoiding a 3rd kernel.
        atomicMin(out, __float_as_uint(0.5f * m));
    }
}

extern "C" void kernel_launch(void* const* d_in, const int* in_sizes, int n_in,
                              void* d_out, int out_size) {
    const float* last_point     = (const float*)d_in[0];  // [64, 64, 2] f32
    const float* polygon_coords = (const float*)d_in[1];  // [64, 128, 32, 2] f32
    unsigned int* out_bits = (unsigned int*)d_out;        // scalar f32 output

    pl_init_kernel<<<1, 1>>>(out_bits);
    pl_main_kernel<<<PN, MN>>>(last_point, polygon_coords, out_bits);
}